// round 14
// baseline (speedup 1.0000x reference)
#include <cuda_runtime.h>
#include <cuda_fp16.h>
#include <cstdint>

#define DN 128
#define CN 86
#define NP 96
#define ETILE 128
#define ETHREADS 512
#define MAX_EDGES 1000000

__device__ __half g_P16[100000 * 256];   // [n][0:128]=h@W1u+b1, [n][128:256]=h@W1v
__device__ int    g_src32[MAX_EDGES];
__device__ int    g_dst32[MAX_EDGES];
__device__ int    g_use64;
__device__ __half g_W2H[NP * DN];        // W2^T [n][k] fp16, rows 86..95 = 0

// ---- edge kernel smem (ETILE=128, depth 2) ----
#define U_PITCH_B   272                  // 136 fp16 per row
#define STAGE_BYTES 69632                // U+V per stage: 2 x 128 x 272
#define OFF_OUTS    139264               // 2 stages
#define SMEM_EDGE_BYTES (OFF_OUTS + ETILE * CN * 4)   // 183296

// ---- node kernel smem ----
#define OFF_W1H     0                    // [256][136] fp16 = 69632 B
#define OFF_HF32    69632                // 2 stages x [64][136] fp32 (34816 B each)
#define HF32_B      34816
#define OFF_HT      (OFF_HF32 + 2 * HF32_B)           // fp16 tile [64][136] = 17408
#define SMEM_NODE_BYTES (OFF_HT + 17408)              // 156672

__device__ __forceinline__ uint32_t smem_u32(const void* p) {
    uint32_t a;
    asm("{ .reg .u64 t; cvta.to.shared.u64 t, %1; cvt.u32.u64 %0, t; }"
        : "=r"(a) : "l"(p));
    return a;
}
__device__ __forceinline__ void cp16(uint32_t dst, const void* gsrc) {
    asm volatile("cp.async.cg.shared.global [%0], [%1], 16;"
                 :: "r"(dst), "l"(__cvta_generic_to_global(gsrc)) : "memory");
}
__device__ __forceinline__ void cp_commit() {
    asm volatile("cp.async.commit_group;" ::: "memory");
}
__device__ __forceinline__ void cp_wait1() {
    asm volatile("cp.async.wait_group 1;" ::: "memory");
}
__device__ __forceinline__ void cp_wait0() {
    asm volatile("cp.async.wait_group 0;" ::: "memory");
}
__device__ __forceinline__ void ldmx4(uint32_t* r, uint32_t addr) {
    asm volatile("ldmatrix.sync.aligned.m8n8.x4.shared.b16 {%0,%1,%2,%3}, [%4];"
                 : "=r"(r[0]), "=r"(r[1]), "=r"(r[2]), "=r"(r[3]) : "r"(addr));
}
__device__ __forceinline__ uint32_t hadd2_(uint32_t a, uint32_t b) {
    uint32_t d; asm("add.f16x2 %0, %1, %2;" : "=r"(d) : "r"(a), "r"(b)); return d;
}
__device__ __forceinline__ uint32_t hrelu2_(uint32_t a) {
    uint32_t d; asm("max.f16x2 %0, %1, %2;" : "=r"(d) : "r"(a), "r"(0u)); return d;
}
__device__ __forceinline__ void mma_f16(float* c, const uint32_t* a, const uint32_t* b) {
    asm volatile(
        "mma.sync.aligned.m16n8k16.row.col.f32.f16.f16.f32 "
        "{%0,%1,%2,%3}, {%4,%5,%6,%7}, {%8,%9}, {%0,%1,%2,%3};"
        : "+f"(c[0]), "+f"(c[1]), "+f"(c[2]), "+f"(c[3])
        : "r"(a[0]), "r"(a[1]), "r"(a[2]), "r"(a[3]), "r"(b[0]), "r"(b[1]));
}

// ---------------------------------------------------------------------------
// Prep kernels
// ---------------------------------------------------------------------------
__global__ void sniff_kernel(const void* src, int n_edges, int n_nodes)
{
    __shared__ int bad;
    if (threadIdx.x == 0) bad = 0;
    __syncthreads();
    const long long* p = (const long long*)src;
    int n_check = n_edges < 1024 ? n_edges : 1024;
    for (int i = threadIdx.x; i < n_check; i += blockDim.x) {
        long long v = p[i];
        if (v < 0 || v >= (long long)n_nodes) atomicOr(&bad, 1);
    }
    __syncthreads();
    if (threadIdx.x == 0) g_use64 = bad ? 0 : 1;
}

__global__ void convert_kernel(const void* src, const void* dst, int n_edges)
{
    int i = blockIdx.x * blockDim.x + threadIdx.x;
    if (i >= n_edges) return;
    if (g_use64) {
        g_src32[i] = (int)((const long long*)src)[i];
        g_dst32[i] = (int)((const long long*)dst)[i];
    } else {
        g_src32[i] = ((const int*)src)[i];
        g_dst32[i] = ((const int*)dst)[i];
    }
}

__global__ void w2h_kernel(const float* __restrict__ W2)
{
    int i = blockIdx.x * blockDim.x + threadIdx.x;
    if (i >= NP * DN) return;
    int n = i >> 7, k = i & 127;
    float v = (n < CN) ? W2[k * CN + n] : 0.f;
    g_W2H[i] = __float2half_rn(v);
}

// ---------------------------------------------------------------------------
// Kernel A: node GEMM on fp16 mma.sync. Persistent. Stages fp32 h via cp16,
// converts fp32->fp16 in smem, then ldmatrix. No separate h16 kernel.
// Tile = 64 nodes x 256 cols. 16 warps: wr=wid&3 (16 rows), wc=wid>>2 (64 cols).
// ---------------------------------------------------------------------------
__global__ void __launch_bounds__(512) node_mma_kernel(
    const float* __restrict__ h, const float* __restrict__ W1,
    const float* __restrict__ b1, int n_nodes, int n_tiles)
{
    extern __shared__ char smem[];
    const uint32_t sbase = smem_u32(smem);
    __half* W1s = reinterpret_cast<__half*>(smem + OFF_W1H);

    const int tid  = threadIdx.x;
    const int wid  = tid >> 5;
    const int lane = tid & 31;
    const int G    = gridDim.x;

    // Stage fused W1' [n=256][k=128] fp16 once (pitch 136 halves).
    for (int i = tid; i < 256 * 128; i += 512) {
        int k = i >> 8, n = i & 255;
        float v = (n < DN) ? W1[(size_t)k * DN + n]
                           : W1[(size_t)(DN + k) * DN + (n - DN)];
        W1s[n * 136 + k] = __float2half_rn(v);
    }

    const int wr = wid & 3;
    const int wc = wid >> 2;
    const int arow0 = wr * 16;

    float bias[8][2];
    #pragma unroll
    for (int j = 0; j < 8; j++) {
        int col = wc * 64 + j * 8 + 2 * (lane & 3);
        bias[j][0] = (col     < DN) ? b1[col]     : 0.f;
        bias[j][1] = (col + 1 < DN) ? b1[col + 1] : 0.f;
    }

    const int e_loc = tid >> 3;      // 0..63
    const int q     = tid & 7;       // 16-float slice of 128-float row

    auto prefetch = [&](int t, int s) {
        if (t < n_tiles) {
            int node = t * 64 + e_loc;
            if (node >= n_nodes) node = 0;
            const float* hs = &h[(size_t)node * 128 + q * 16];
            uint32_t hd = sbase + OFF_HF32 + s * HF32_B + e_loc * 544 + q * 64;
            cp16(hd,      hs);
            cp16(hd + 16, hs + 4);
            cp16(hd + 32, hs + 8);
            cp16(hd + 48, hs + 12);
        }
        cp_commit();
    };

    const uint32_t a_off = (uint32_t)(arow0 + (lane & 15)) * U_PITCH_B + (lane >> 4) * 16;
    const uint32_t b_row = (uint32_t)(wc * 64 + (lane & 7) + ((lane >> 4) & 1) * 8);
    const uint32_t b_off = b_row * U_PITCH_B + ((lane >> 3) & 1) * 16;
    const uint32_t wb    = sbase + OFF_W1H + b_off;

    __syncthreads();   // W1s ready

    int stage = 0;
    prefetch(blockIdx.x, 0);

    for (int t = blockIdx.x; t < n_tiles; t += G) {
        prefetch(t + G, stage ^ 1);
        cp_wait1();
        __syncthreads();

        // Convert fp32 stage -> fp16 tile (HT).
        {
            const float* fs = reinterpret_cast<const float*>(smem + OFF_HF32 + stage * HF32_B)
                              + e_loc * 136 + q * 16;
            __half* hd = reinterpret_cast<__half*>(smem + OFF_HT) + e_loc * 136 + q * 16;
            #pragma unroll
            for (int i = 0; i < 4; i++) {
                float4 v = *reinterpret_cast<const float4*>(fs + 4 * i);
                __half2 lo = __floats2half2_rn(v.x, v.y);
                __half2 hi = __floats2half2_rn(v.z, v.w);
                uint2 bits = make_uint2(*reinterpret_cast<uint32_t*>(&lo),
                                        *reinterpret_cast<uint32_t*>(&hi));
                *reinterpret_cast<uint2*>(hd + 4 * i) = bits;
            }
        }
        __syncthreads();

        const uint32_t ub = sbase + OFF_HT + a_off;

        float c[8][4];
        #pragma unroll
        for (int j = 0; j < 8; j++)
            #pragma unroll
            for (int r = 0; r < 4; r++) c[j][r] = 0.f;

        #pragma unroll
        for (int kk = 0; kk < 8; kk++) {
            uint32_t a[4];
            ldmx4(a, ub + kk * 32);
            #pragma unroll
            for (int p = 0; p < 4; p++) {
                uint32_t bq[4];
                ldmx4(bq, wb + p * 16 * U_PITCH_B + kk * 32);
                mma_f16(c[2 * p],     a, bq);
                mma_f16(c[2 * p + 1], a, bq + 2);
            }
        }

        {
            const int r0 = t * 64 + arow0 + (lane >> 2);
            #pragma unroll
            for (int j = 0; j < 8; j++) {
                int col = wc * 64 + j * 8 + 2 * (lane & 3);
                if (r0 < n_nodes) {
                    __half2 v = __floats2half2_rn(c[j][0] + bias[j][0],
                                                  c[j][1] + bias[j][1]);
                    *reinterpret_cast<uint32_t*>(&g_P16[(size_t)r0 * 256 + col]) =
                        *reinterpret_cast<uint32_t*>(&v);
                }
                if (r0 + 8 < n_nodes) {
                    __half2 v = __floats2half2_rn(c[j][2] + bias[j][0],
                                                  c[j][3] + bias[j][1]);
                    *reinterpret_cast<uint32_t*>(&g_P16[(size_t)(r0 + 8) * 256 + col]) =
                        *reinterpret_cast<uint32_t*>(&v);
                }
            }
        }
        __syncthreads();   // HT + fp32 stage reads done
        stage ^= 1;
    }
    cp_wait0();
}

// ---------------------------------------------------------------------------
// Kernel B: persistent fp16 edge MLP. ETILE=128, depth-2 cp16 pipeline.
// 16 warps: wr=wid&3 (32 rows = 2 m16-tiles), wc=wid>>2 (24 cols = 3 n8-tiles).
// Register-resident W2; relu-add fused on fragments.
// ---------------------------------------------------------------------------
__global__ void __launch_bounds__(ETHREADS) edge_mma_kernel(
    const float* __restrict__ b2, float* __restrict__ out,
    int n_edges, int n_tiles)
{
    extern __shared__ char smem[];
    const uint32_t sbase = smem_u32(smem);
    float* OUTS = reinterpret_cast<float*>(smem + OFF_OUTS);

    const int tid  = threadIdx.x;
    const int wid  = tid >> 5;
    const int lane = tid & 31;
    const int G    = gridDim.x;

    const int e_loc = tid >> 2;      // 0..127
    const int q     = tid & 3;       // 64B slice of 256B row

    const int wr = wid & 3;
    const int wc = wid >> 2;
    const int arow0 = wr * 32;

    uint32_t bf[3][8][2];
    {
        const int n = wc * 24 + (lane >> 2);
        const int k2 = 2 * (lane & 3);
        #pragma unroll
        for (int j = 0; j < 3; j++) {
            const __half* rowp = &g_W2H[(n + j * 8) * DN];
            #pragma unroll
            for (int kk = 0; kk < 8; kk++) {
                bf[j][kk][0] = *reinterpret_cast<const uint32_t*>(rowp + kk * 16 + k2);
                bf[j][kk][1] = *reinterpret_cast<const uint32_t*>(rowp + kk * 16 + k2 + 8);
            }
        }
    }
    float bias[3][2];
    #pragma unroll
    for (int j = 0; j < 3; j++) {
        int col = wc * 24 + j * 8 + 2 * (lane & 3);
        bias[j][0] = (col     < CN) ? b2[col]     : 0.f;
        bias[j][1] = (col + 1 < CN) ? b2[col + 1] : 0.f;
    }

    auto prefetch = [&](int t, int s) {
        if (t < n_tiles) {
            int eg = t * ETILE + e_loc;
            int si = 0, di = 0;
            if (eg < n_edges) { si = __ldg(&g_src32[eg]); di = __ldg(&g_dst32[eg]); }
            const __half* us = &g_P16[(size_t)si * 256 + q * 32];
            const __half* vs = &g_P16[(size_t)di * 256 + 128 + q * 32];
            uint32_t ud = sbase + s * STAGE_BYTES + e_loc * U_PITCH_B + q * 64;
            uint32_t vd = ud + 34816;
            cp16(ud,      us);
            cp16(ud + 16, us + 8);
            cp16(ud + 32, us + 16);
            cp16(ud + 48, us + 24);
            cp16(vd,      vs);
            cp16(vd + 16, vs + 8);
            cp16(vd + 32, vs + 16);
            cp16(vd + 48, vs + 24);
        }
        cp_commit();
    };

    const uint32_t a_off = (uint32_t)(arow0 + (lane & 15)) * U_PITCH_B + (lane >> 4) * 16;

    int stage = 0;
    prefetch(blockIdx.x, 0);

    for (int t = blockIdx.x; t < n_tiles; t += G) {
        prefetch(t + G, stage ^ 1);
        cp_wait1();
        __syncthreads();

        const uint32_t ub = sbase + stage * STAGE_BYTES + a_off;
        const uint32_t vb = ub + 34816;

        float c[2][3][4];
        #pragma unroll
        for (int t2 = 0; t2 < 2; t2++)
            #pragma unroll
            for (int j = 0; j < 3; j++)
                #pragma unroll
                for (int r = 0; r < 4; r++) c[t2][j][r] = 0.f;

        #pragma unroll
        for (int kk = 0; kk < 8; kk++) {
            #pragma unroll
            for (int t2 = 0; t2 < 2; t2++) {
                uint32_t au[4], av[4], a[4];
                ldmx4(au, ub + t2 * 16 * U_PITCH_B + kk * 32);
                ldmx4(av, vb + t2 * 16 * U_PITCH_B + kk * 32);
                #pragma unroll
                for (int r = 0; r < 4; r++)
                    a[r] = hrelu2_(hadd2_(au[r], av[r]));
                #pragma unroll
                for (int j = 0; j < 3; j++)
                    mma_f16(c[t2][j], a, bf[j][kk]);
            }
        }
        __syncthreads();   // all reads of U/V[stage] done before refill

        {
            const int row = arow0 + (lane >> 2);
            #pragma unroll
            for (int t2 = 0; t2 < 2; t2++) {
                #pragma unroll
                for (int j = 0; j < 3; j++) {
                    int col = wc * 24 + j * 8 + 2 * (lane & 3);
                    int rr = row + t2 * 16;
                    if (col < CN) {
                        OUTS[rr * CN + col]       = c[t2][j][0] + bias[j][0];
                        OUTS[(rr + 8) * CN + col] = c[t2][j][2] + bias[j][0];
                    }
                    if (col + 1 < CN) {
                        OUTS[rr * CN + col + 1]       = c[t2][j][1] + bias[j][1];
                        OUTS[(rr + 8) * CN + col + 1] = c[t2][j][3] + bias[j][1];
                    }
                }
            }
        }
        __syncthreads();

        int e0 = t * ETILE;
        int valid = n_edges - e0;
        if (valid > ETILE) valid = ETILE;
        float* dstp = out + (size_t)e0 * CN;
        if (valid == ETILE) {
            const float4* s4 = reinterpret_cast<const float4*>(OUTS);
            float4* d4 = reinterpret_cast<float4*>(dstp);
            #pragma unroll
            for (int i = tid; i < ETILE * CN / 4; i += ETHREADS) d4[i] = s4[i];
        } else {
            for (int i = tid; i < valid * CN; i += ETHREADS) dstp[i] = OUTS[i];
        }
        __syncthreads();
        stage ^= 1;
    }
    cp_wait0();
}

// ---------------------------------------------------------------------------
extern "C" void kernel_launch(void* const* d_in, const int* in_sizes, int n_in,
                              void* d_out, int out_size)
{
    const float* h   = (const float*)d_in[0];
    const float* W1  = (const float*)d_in[1];
    const float* b1  = (const float*)d_in[2];
    const float* W2  = (const float*)d_in[3];
    const float* b2  = (const float*)d_in[4];
    const void*  src = d_in[5];
    const void*  dst = d_in[6];
    float* out = (float*)d_out;

    const int n_nodes = in_sizes[0] / DN;
    const int n_edges = in_sizes[5];

    static int n_sm = 0;
    if (n_sm == 0) {
        cudaDeviceGetAttribute(&n_sm, cudaDevAttrMultiProcessorCount, 0);
        if (n_sm <= 0) n_sm = 148;
    }

    sniff_kernel<<<1, 256>>>(src, n_edges, n_nodes);
    convert_kernel<<<(n_edges + 255) / 256, 256>>>(src, dst, n_edges);
    w2h_kernel<<<(NP * DN + 255) / 256, 256>>>(W2);

    cudaFuncSetAttribute(node_mma_kernel, cudaFuncAttributeMaxDynamicSharedMemorySize, SMEM_NODE_BYTES);
    cudaFuncSetAttribute(edge_mma_kernel, cudaFuncAttributeMaxDynamicSharedMemorySize, SMEM_EDGE_BYTES);

    int n_tiles_node = (n_nodes + 63) / 64;
    node_mma_kernel<<<n_sm, 512, SMEM_NODE_BYTES>>>(h, W1, b1, n_nodes, n_tiles_node);

    int n_tiles = (n_edges + ETILE - 1) / ETILE;
    edge_mma_kernel<<<n_sm, ETHREADS, SMEM_EDGE_BYTES>>>(b2, out, n_edges, n_tiles);
}

// round 15
// speedup vs baseline: 1.4805x; 1.4805x over previous
#include <cuda_runtime.h>
#include <cuda_fp16.h>
#include <cstdint>

#define DN 128
#define CN 86
#define NP 96
#define ETILE 64
#define ETHREADS 512
#define MAX_EDGES 1000000

__device__ __half g_P16[100000 * 256];   // [n][0:128]=h@W1u+b1, [n][128:256]=h@W1v
__device__ int    g_src32[MAX_EDGES];
__device__ int    g_dst32[MAX_EDGES];
__device__ int    g_use64;
__device__ __half g_W2H[NP * DN];        // W2^T [n][k] fp16, rows 86..95 = 0

// ---- edge kernel smem (R11 layout: ETILE=64, depth 3) ----
#define U_PITCH_B   272                  // 136 fp16 per row
#define ESTAGE_B    34816                // U+V per stage (2 x 64 x 272)
#define OFF_EOUTS   104448               // 3 stages
#define SMEM_EDGE_BYTES (OFF_EOUTS + ETILE * CN * 4)   // 126464

// ---- node kernel smem (R14 layout) ----
#define OFF_W1H     0                    // [256][136] fp16 = 69632 B
#define OFF_HF32    69632                // 2 stages x [64][136] fp32
#define HF32_B      34816
#define OFF_HT      (OFF_HF32 + 2 * HF32_B)   // fp16 tile [64][136]
#define SMEM_NODE_BYTES (OFF_HT + 17408)      // 156672

__device__ __forceinline__ uint32_t smem_u32(const void* p) {
    uint32_t a;
    asm("{ .reg .u64 t; cvta.to.shared.u64 t, %1; cvt.u32.u64 %0, t; }"
        : "=r"(a) : "l"(p));
    return a;
}
__device__ __forceinline__ void cp16(uint32_t dst, const void* gsrc) {
    asm volatile("cp.async.cg.shared.global [%0], [%1], 16;"
                 :: "r"(dst), "l"(__cvta_generic_to_global(gsrc)) : "memory");
}
__device__ __forceinline__ void cp_commit() {
    asm volatile("cp.async.commit_group;" ::: "memory");
}
__device__ __forceinline__ void cp_wait1() {
    asm volatile("cp.async.wait_group 1;" ::: "memory");
}
__device__ __forceinline__ void cp_wait2() {
    asm volatile("cp.async.wait_group 2;" ::: "memory");
}
__device__ __forceinline__ void cp_wait0() {
    asm volatile("cp.async.wait_group 0;" ::: "memory");
}
__device__ __forceinline__ void ldmx4(uint32_t* r, uint32_t addr) {
    asm volatile("ldmatrix.sync.aligned.m8n8.x4.shared.b16 {%0,%1,%2,%3}, [%4];"
                 : "=r"(r[0]), "=r"(r[1]), "=r"(r[2]), "=r"(r[3]) : "r"(addr));
}
__device__ __forceinline__ uint32_t hadd2_(uint32_t a, uint32_t b) {
    uint32_t d; asm("add.f16x2 %0, %1, %2;" : "=r"(d) : "r"(a), "r"(b)); return d;
}
__device__ __forceinline__ uint32_t hrelu2_(uint32_t a) {
    uint32_t d; asm("max.f16x2 %0, %1, %2;" : "=r"(d) : "r"(a), "r"(0u)); return d;
}
__device__ __forceinline__ void mma_f16(float* c, const uint32_t* a, const uint32_t* b) {
    asm volatile(
        "mma.sync.aligned.m16n8k16.row.col.f32.f16.f16.f32 "
        "{%0,%1,%2,%3}, {%4,%5,%6,%7}, {%8,%9}, {%0,%1,%2,%3};"
        : "+f"(c[0]), "+f"(c[1]), "+f"(c[2]), "+f"(c[3])
        : "r"(a[0]), "r"(a[1]), "r"(a[2]), "r"(a[3]), "r"(b[0]), "r"(b[1]));
}

// ---------------------------------------------------------------------------
// Prep kernels
// ---------------------------------------------------------------------------
__global__ void sniff_kernel(const void* src, int n_edges, int n_nodes)
{
    __shared__ int bad;
    if (threadIdx.x == 0) bad = 0;
    __syncthreads();
    const long long* p = (const long long*)src;
    int n_check = n_edges < 1024 ? n_edges : 1024;
    for (int i = threadIdx.x; i < n_check; i += blockDim.x) {
        long long v = p[i];
        if (v < 0 || v >= (long long)n_nodes) atomicOr(&bad, 1);
    }
    __syncthreads();
    if (threadIdx.x == 0) g_use64 = bad ? 0 : 1;
}

__global__ void convert_kernel(const void* src, const void* dst, int n_edges)
{
    int i = blockIdx.x * blockDim.x + threadIdx.x;
    if (i >= n_edges) return;
    if (g_use64) {
        g_src32[i] = (int)((const long long*)src)[i];
        g_dst32[i] = (int)((const long long*)dst)[i];
    } else {
        g_src32[i] = ((const int*)src)[i];
        g_dst32[i] = ((const int*)dst)[i];
    }
}

__global__ void w2h_kernel(const float* __restrict__ W2)
{
    int i = blockIdx.x * blockDim.x + threadIdx.x;
    if (i >= NP * DN) return;
    int n = i >> 7, k = i & 127;
    float v = (n < CN) ? W2[k * CN + n] : 0.f;
    g_W2H[i] = __float2half_rn(v);
}

// ---------------------------------------------------------------------------
// Kernel A: node GEMM on fp16 mma.sync (R14 version — fp32 staging + convert).
// ---------------------------------------------------------------------------
__global__ void __launch_bounds__(512) node_mma_kernel(
    const float* __restrict__ h, const float* __restrict__ W1,
    const float* __restrict__ b1, int n_nodes, int n_tiles)
{
    extern __shared__ char smem[];
    const uint32_t sbase = smem_u32(smem);
    __half* W1s = reinterpret_cast<__half*>(smem + OFF_W1H);

    const int tid  = threadIdx.x;
    const int wid  = tid >> 5;
    const int lane = tid & 31;
    const int G    = gridDim.x;

    for (int i = tid; i < 256 * 128; i += 512) {
        int k = i >> 8, n = i & 255;
        float v = (n < DN) ? W1[(size_t)k * DN + n]
                           : W1[(size_t)(DN + k) * DN + (n - DN)];
        W1s[n * 136 + k] = __float2half_rn(v);
    }

    const int wr = wid & 3;
    const int wc = wid >> 2;
    const int arow0 = wr * 16;

    float bias[8][2];
    #pragma unroll
    for (int j = 0; j < 8; j++) {
        int col = wc * 64 + j * 8 + 2 * (lane & 3);
        bias[j][0] = (col     < DN) ? b1[col]     : 0.f;
        bias[j][1] = (col + 1 < DN) ? b1[col + 1] : 0.f;
    }

    const int e_loc = tid >> 3;      // 0..63
    const int q     = tid & 7;       // 16-float slice

    auto prefetch = [&](int t, int s) {
        if (t < n_tiles) {
            int node = t * 64 + e_loc;
            if (node >= n_nodes) node = 0;
            const float* hs = &h[(size_t)node * 128 + q * 16];
            uint32_t hd = sbase + OFF_HF32 + s * HF32_B + e_loc * 544 + q * 64;
            cp16(hd,      hs);
            cp16(hd + 16, hs + 4);
            cp16(hd + 32, hs + 8);
            cp16(hd + 48, hs + 12);
        }
        cp_commit();
    };

    const uint32_t a_off = (uint32_t)(arow0 + (lane & 15)) * U_PITCH_B + (lane >> 4) * 16;
    const uint32_t b_row = (uint32_t)(wc * 64 + (lane & 7) + ((lane >> 4) & 1) * 8);
    const uint32_t b_off = b_row * U_PITCH_B + ((lane >> 3) & 1) * 16;
    const uint32_t wb    = sbase + OFF_W1H + b_off;

    __syncthreads();   // W1s ready

    int stage = 0;
    prefetch(blockIdx.x, 0);

    for (int t = blockIdx.x; t < n_tiles; t += G) {
        prefetch(t + G, stage ^ 1);
        cp_wait1();
        __syncthreads();

        // fp32 stage -> fp16 tile
        {
            const float* fs = reinterpret_cast<const float*>(smem + OFF_HF32 + stage * HF32_B)
                              + e_loc * 136 + q * 16;
            __half* hd = reinterpret_cast<__half*>(smem + OFF_HT) + e_loc * 136 + q * 16;
            #pragma unroll
            for (int i = 0; i < 4; i++) {
                float4 v = *reinterpret_cast<const float4*>(fs + 4 * i);
                __half2 lo = __floats2half2_rn(v.x, v.y);
                __half2 hi = __floats2half2_rn(v.z, v.w);
                uint2 bits = make_uint2(*reinterpret_cast<uint32_t*>(&lo),
                                        *reinterpret_cast<uint32_t*>(&hi));
                *reinterpret_cast<uint2*>(hd + 4 * i) = bits;
            }
        }
        __syncthreads();

        const uint32_t ub = sbase + OFF_HT + a_off;

        float c[8][4];
        #pragma unroll
        for (int j = 0; j < 8; j++)
            #pragma unroll
            for (int r = 0; r < 4; r++) c[j][r] = 0.f;

        #pragma unroll
        for (int kk = 0; kk < 8; kk++) {
            uint32_t a[4];
            ldmx4(a, ub + kk * 32);
            #pragma unroll
            for (int p = 0; p < 4; p++) {
                uint32_t bq[4];
                ldmx4(bq, wb + p * 16 * U_PITCH_B + kk * 32);
                mma_f16(c[2 * p],     a, bq);
                mma_f16(c[2 * p + 1], a, bq + 2);
            }
        }

        {
            const int r0 = t * 64 + arow0 + (lane >> 2);
            #pragma unroll
            for (int j = 0; j < 8; j++) {
                int col = wc * 64 + j * 8 + 2 * (lane & 3);
                if (r0 < n_nodes) {
                    __half2 v = __floats2half2_rn(c[j][0] + bias[j][0],
                                                  c[j][1] + bias[j][1]);
                    *reinterpret_cast<uint32_t*>(&g_P16[(size_t)r0 * 256 + col]) =
                        *reinterpret_cast<uint32_t*>(&v);
                }
                if (r0 + 8 < n_nodes) {
                    __half2 v = __floats2half2_rn(c[j][2] + bias[j][0],
                                                  c[j][3] + bias[j][1]);
                    *reinterpret_cast<uint32_t*>(&g_P16[(size_t)(r0 + 8) * 256 + col]) =
                        *reinterpret_cast<uint32_t*>(&v);
                }
            }
        }
        __syncthreads();
        stage ^= 1;
    }
    cp_wait0();
}

// ---------------------------------------------------------------------------
// Kernel B: persistent fp16 edge MLP (R11 version — ETILE=64, depth-3 cp16).
// ---------------------------------------------------------------------------
__global__ void __launch_bounds__(ETHREADS) edge_mma_kernel(
    const float* __restrict__ b2, float* __restrict__ out,
    int n_edges, int n_tiles)
{
    extern __shared__ char smem[];
    const uint32_t sbase = smem_u32(smem);
    float* OUTS = reinterpret_cast<float*>(smem + OFF_EOUTS);

    const int tid  = threadIdx.x;
    const int wid  = tid >> 5;
    const int lane = tid & 31;
    const int G    = gridDim.x;

    const int e_loc = tid >> 3;     // 0..63
    const int q     = tid & 7;      // 16-fp16 slice

    const int wr = wid & 3;
    const int wc = wid >> 2;
    const int arow0 = wr * 16;

    uint32_t bf[3][8][2];
    {
        const int n = wc * 24 + (lane >> 2);
        const int k2 = 2 * (lane & 3);
        #pragma unroll
        for (int j = 0; j < 3; j++) {
            const __half* rowp = &g_W2H[(n + j * 8) * DN];
            #pragma unroll
            for (int kk = 0; kk < 8; kk++) {
                bf[j][kk][0] = *reinterpret_cast<const uint32_t*>(rowp + kk * 16 + k2);
                bf[j][kk][1] = *reinterpret_cast<const uint32_t*>(rowp + kk * 16 + k2 + 8);
            }
        }
    }
    float bias[3][2];
    #pragma unroll
    for (int j = 0; j < 3; j++) {
        int col = wc * 24 + j * 8 + 2 * (lane & 3);
        bias[j][0] = (col     < CN) ? b2[col]     : 0.f;
        bias[j][1] = (col + 1 < CN) ? b2[col + 1] : 0.f;
    }

    auto prefetch = [&](int t, int s) {
        if (t < n_tiles) {
            int eg = t * ETILE + e_loc;
            int si = 0, di = 0;
            if (eg < n_edges) { si = __ldg(&g_src32[eg]); di = __ldg(&g_dst32[eg]); }
            const __half* us = &g_P16[(size_t)si * 256 + q * 16];
            const __half* vs = &g_P16[(size_t)di * 256 + 128 + q * 16];
            uint32_t ud = sbase + s * ESTAGE_B + e_loc * U_PITCH_B + q * 32;
            uint32_t vd = ud + 17408;
            cp16(ud,      us);
            cp16(ud + 16, us + 8);
            cp16(vd,      vs);
            cp16(vd + 16, vs + 8);
        }
        cp_commit();
    };

    const uint32_t a_off = (uint32_t)(arow0 + (lane & 15)) * U_PITCH_B + (lane >> 4) * 16;

    int stage = 0;
    prefetch(blockIdx.x, 0);
    prefetch(blockIdx.x + G, 1);

    for (int t = blockIdx.x; t < n_tiles; t += G) {
        prefetch(t + 2 * G, (stage + 2) % 3);
        cp_wait2();
        __syncthreads();

        const uint32_t ub = sbase + stage * ESTAGE_B + a_off;
        const uint32_t vb = ub + 17408;

        float c[3][4];
        #pragma unroll
        for (int j = 0; j < 3; j++)
            #pragma unroll
            for (int r = 0; r < 4; r++) c[j][r] = 0.f;

        #pragma unroll
        for (int kk = 0; kk < 8; kk++) {
            uint32_t au[4], av[4], a[4];
            ldmx4(au, ub + kk * 32);
            ldmx4(av, vb + kk * 32);
            #pragma unroll
            for (int r = 0; r < 4; r++)
                a[r] = hrelu2_(hadd2_(au[r], av[r]));
            #pragma unroll
            for (int j = 0; j < 3; j++)
                mma_f16(c[j], a, bf[j][kk]);
        }
        __syncthreads();

        {
            const int row = arow0 + (lane >> 2);
            #pragma unroll
            for (int j = 0; j < 3; j++) {
                int col = wc * 24 + j * 8 + 2 * (lane & 3);
                if (col < CN) {
                    OUTS[row * CN + col]       = c[j][0] + bias[j][0];
                    OUTS[(row + 8) * CN + col] = c[j][2] + bias[j][0];
                }
                if (col + 1 < CN) {
                    OUTS[row * CN + col + 1]       = c[j][1] + bias[j][1];
                    OUTS[(row + 8) * CN + col + 1] = c[j][3] + bias[j][1];
                }
            }
        }
        __syncthreads();

        int e0 = t * ETILE;
        int valid = n_edges - e0;
        if (valid > ETILE) valid = ETILE;
        float* dstp = out + (size_t)e0 * CN;
        if (valid == ETILE) {
            const float4* s4 = reinterpret_cast<const float4*>(OUTS);
            float4* d4 = reinterpret_cast<float4*>(dstp);
            #pragma unroll
            for (int i = tid; i < ETILE * CN / 4; i += ETHREADS) d4[i] = s4[i];
        } else {
            for (int i = tid; i < valid * CN; i += ETHREADS) dstp[i] = OUTS[i];
        }
        __syncthreads();
        stage = (stage + 1) % 3;
    }
    cp_wait0();
}

// ---------------------------------------------------------------------------
extern "C" void kernel_launch(void* const* d_in, const int* in_sizes, int n_in,
                              void* d_out, int out_size)
{
    const float* h   = (const float*)d_in[0];
    const float* W1  = (const float*)d_in[1];
    const float* b1  = (const float*)d_in[2];
    const float* W2  = (const float*)d_in[3];
    const float* b2  = (const float*)d_in[4];
    const void*  src = d_in[5];
    const void*  dst = d_in[6];
    float* out = (float*)d_out;

    const int n_nodes = in_sizes[0] / DN;
    const int n_edges = in_sizes[5];

    static int n_sm = 0;
    if (n_sm == 0) {
        cudaDeviceGetAttribute(&n_sm, cudaDevAttrMultiProcessorCount, 0);
        if (n_sm <= 0) n_sm = 148;
    }

    sniff_kernel<<<1, 256>>>(src, n_edges, n_nodes);
    convert_kernel<<<(n_edges + 255) / 256, 256>>>(src, dst, n_edges);
    w2h_kernel<<<(NP * DN + 255) / 256, 256>>>(W2);

    cudaFuncSetAttribute(node_mma_kernel, cudaFuncAttributeMaxDynamicSharedMemorySize, SMEM_NODE_BYTES);
    cudaFuncSetAttribute(edge_mma_kernel, cudaFuncAttributeMaxDynamicSharedMemorySize, SMEM_EDGE_BYTES);

    int n_tiles_node = (n_nodes + 63) / 64;
    node_mma_kernel<<<n_sm, 512, SMEM_NODE_BYTES>>>(h, W1, b1, n_nodes, n_tiles_node);

    int n_tiles = (n_edges + ETILE - 1) / ETILE;
    edge_mma_kernel<<<n_sm, ETHREADS, SMEM_EDGE_BYTES>>>(b2, out, n_edges, n_tiles);
}

// round 17
// speedup vs baseline: 1.7345x; 1.1715x over previous
#include <cuda_runtime.h>
#include <cuda_fp16.h>
#include <cstdint>

#define DN 128
#define CN 86
#define NP 96
#define ETILE 32
#define ETHREADS 256
#define MAX_EDGES 1000000

__device__ __half g_P16[100000 * 256];   // [n][0:128]=h@W1u+b1, [n][128:256]=h@W1v
__device__ int    g_src32[MAX_EDGES];
__device__ int    g_dst32[MAX_EDGES];
__device__ int    g_use64;
__device__ __half g_W2H[NP * DN];        // W2^T [n][k] fp16, rows 86..95 = 0

// ---- edge kernel smem (ETILE=32, depth 3, 2 CTAs/SM) ----
#define U_PITCH_B   272                  // 136 fp16 per row
#define ESTAGE_B    17408                // U+V per stage (2 x 32 x 272)
#define OFF_EOUTS   52224                // 3 stages
#define SMEM_EDGE_BYTES (OFF_EOUTS + ETILE * CN * 4)   // 63232 -> 2 CTAs/SM

// ---- node kernel smem (R14/R15 layout) ----
#define OFF_W1H     0                    // [256][136] fp16 = 69632 B
#define OFF_HF32    69632                // 2 stages x [64][136] fp32
#define HF32_B      34816
#define OFF_HT      (OFF_HF32 + 2 * HF32_B)   // fp16 tile [64][136]
#define SMEM_NODE_BYTES (OFF_HT + 17408)      // 156672

__device__ __forceinline__ uint32_t smem_u32(const void* p) {
    uint32_t a;
    asm("{ .reg .u64 t; cvta.to.shared.u64 t, %1; cvt.u32.u64 %0, t; }"
        : "=r"(a) : "l"(p));
    return a;
}
__device__ __forceinline__ void cp16(uint32_t dst, const void* gsrc) {
    asm volatile("cp.async.cg.shared.global [%0], [%1], 16;"
                 :: "r"(dst), "l"(__cvta_generic_to_global(gsrc)) : "memory");
}
__device__ __forceinline__ void cp_commit() {
    asm volatile("cp.async.commit_group;" ::: "memory");
}
__device__ __forceinline__ void cp_wait1() {
    asm volatile("cp.async.wait_group 1;" ::: "memory");
}
__device__ __forceinline__ void cp_wait2() {
    asm volatile("cp.async.wait_group 2;" ::: "memory");
}
__device__ __forceinline__ void cp_wait0() {
    asm volatile("cp.async.wait_group 0;" ::: "memory");
}
__device__ __forceinline__ void ldmx4(uint32_t* r, uint32_t addr) {
    asm volatile("ldmatrix.sync.aligned.m8n8.x4.shared.b16 {%0,%1,%2,%3}, [%4];"
                 : "=r"(r[0]), "=r"(r[1]), "=r"(r[2]), "=r"(r[3]) : "r"(addr));
}
__device__ __forceinline__ uint32_t hadd2_(uint32_t a, uint32_t b) {
    uint32_t d; asm("add.f16x2 %0, %1, %2;" : "=r"(d) : "r"(a), "r"(b)); return d;
}
__device__ __forceinline__ uint32_t hrelu2_(uint32_t a) {
    uint32_t d; asm("max.f16x2 %0, %1, %2;" : "=r"(d) : "r"(a), "r"(0u)); return d;
}
__device__ __forceinline__ void mma_f16(float* c, const uint32_t* a, const uint32_t* b) {
    asm volatile(
        "mma.sync.aligned.m16n8k16.row.col.f32.f16.f16.f32 "
        "{%0,%1,%2,%3}, {%4,%5,%6,%7}, {%8,%9}, {%0,%1,%2,%3};"
        : "+f"(c[0]), "+f"(c[1]), "+f"(c[2]), "+f"(c[3])
        : "r"(a[0]), "r"(a[1]), "r"(a[2]), "r"(a[3]), "r"(b[0]), "r"(b[1]));
}

// ---------------------------------------------------------------------------
// Prep kernels
// ---------------------------------------------------------------------------
__global__ void sniff_kernel(const void* src, int n_edges, int n_nodes)
{
    __shared__ int bad;
    if (threadIdx.x == 0) bad = 0;
    __syncthreads();
    const long long* p = (const long long*)src;
    int n_check = n_edges < 1024 ? n_edges : 1024;
    for (int i = threadIdx.x; i < n_check; i += blockDim.x) {
        long long v = p[i];
        if (v < 0 || v >= (long long)n_nodes) atomicOr(&bad, 1);
    }
    __syncthreads();
    if (threadIdx.x == 0) g_use64 = bad ? 0 : 1;
}

__global__ void convert_kernel(const void* src, const void* dst, int n_edges)
{
    int i = blockIdx.x * blockDim.x + threadIdx.x;
    if (i >= n_edges) return;
    if (g_use64) {
        g_src32[i] = (int)((const long long*)src)[i];
        g_dst32[i] = (int)((const long long*)dst)[i];
    } else {
        g_src32[i] = ((const int*)src)[i];
        g_dst32[i] = ((const int*)dst)[i];
    }
}

__global__ void w2h_kernel(const float* __restrict__ W2)
{
    int i = blockIdx.x * blockDim.x + threadIdx.x;
    if (i >= NP * DN) return;
    int n = i >> 7, k = i & 127;
    float v = (n < CN) ? W2[k * CN + n] : 0.f;
    g_W2H[i] = __float2half_rn(v);
}

// ---------------------------------------------------------------------------
// Kernel A: node GEMM on fp16 mma.sync (unchanged from R15).
// ---------------------------------------------------------------------------
__global__ void __launch_bounds__(512) node_mma_kernel(
    const float* __restrict__ h, const float* __restrict__ W1,
    const float* __restrict__ b1, int n_nodes, int n_tiles)
{
    extern __shared__ char smem[];
    const uint32_t sbase = smem_u32(smem);
    __half* W1s = reinterpret_cast<__half*>(smem + OFF_W1H);

    const int tid  = threadIdx.x;
    const int wid  = tid >> 5;
    const int lane = tid & 31;
    const int G    = gridDim.x;

    for (int i = tid; i < 256 * 128; i += 512) {
        int k = i >> 8, n = i & 255;
        float v = (n < DN) ? W1[(size_t)k * DN + n]
                           : W1[(size_t)(DN + k) * DN + (n - DN)];
        W1s[n * 136 + k] = __float2half_rn(v);
    }

    const int wr = wid & 3;
    const int wc = wid >> 2;
    const int arow0 = wr * 16;

    float bias[8][2];
    #pragma unroll
    for (int j = 0; j < 8; j++) {
        int col = wc * 64 + j * 8 + 2 * (lane & 3);
        bias[j][0] = (col     < DN) ? b1[col]     : 0.f;
        bias[j][1] = (col + 1 < DN) ? b1[col + 1] : 0.f;
    }

    const int e_loc = tid >> 3;
    const int q     = tid & 7;

    auto prefetch = [&](int t, int s) {
        if (t < n_tiles) {
            int node = t * 64 + e_loc;
            if (node >= n_nodes) node = 0;
            const float* hs = &h[(size_t)node * 128 + q * 16];
            uint32_t hd = sbase + OFF_HF32 + s * HF32_B + e_loc * 544 + q * 64;
            cp16(hd,      hs);
            cp16(hd + 16, hs + 4);
            cp16(hd + 32, hs + 8);
            cp16(hd + 48, hs + 12);
        }
        cp_commit();
    };

    const uint32_t a_off = (uint32_t)(arow0 + (lane & 15)) * U_PITCH_B + (lane >> 4) * 16;
    const uint32_t b_row = (uint32_t)(wc * 64 + (lane & 7) + ((lane >> 4) & 1) * 8);
    const uint32_t b_off = b_row * U_PITCH_B + ((lane >> 3) & 1) * 16;
    const uint32_t wb    = sbase + OFF_W1H + b_off;

    __syncthreads();

    int stage = 0;
    prefetch(blockIdx.x, 0);

    for (int t = blockIdx.x; t < n_tiles; t += G) {
        prefetch(t + G, stage ^ 1);
        cp_wait1();
        __syncthreads();

        {
            const float* fs = reinterpret_cast<const float*>(smem + OFF_HF32 + stage * HF32_B)
                              + e_loc * 136 + q * 16;
            __half* hd = reinterpret_cast<__half*>(smem + OFF_HT) + e_loc * 136 + q * 16;
            #pragma unroll
            for (int i = 0; i < 4; i++) {
                float4 v = *reinterpret_cast<const float4*>(fs + 4 * i);
                __half2 lo = __floats2half2_rn(v.x, v.y);
                __half2 hi = __floats2half2_rn(v.z, v.w);
                uint2 bits = make_uint2(*reinterpret_cast<uint32_t*>(&lo),
                                        *reinterpret_cast<uint32_t*>(&hi));
                *reinterpret_cast<uint2*>(hd + 4 * i) = bits;
            }
        }
        __syncthreads();

        const uint32_t ub = sbase + OFF_HT + a_off;

        float c[8][4];
        #pragma unroll
        for (int j = 0; j < 8; j++)
            #pragma unroll
            for (int r = 0; r < 4; r++) c[j][r] = 0.f;

        #pragma unroll
        for (int kk = 0; kk < 8; kk++) {
            uint32_t a[4];
            ldmx4(a, ub + kk * 32);
            #pragma unroll
            for (int p = 0; p < 4; p++) {
                uint32_t bq[4];
                ldmx4(bq, wb + p * 16 * U_PITCH_B + kk * 32);
                mma_f16(c[2 * p],     a, bq);
                mma_f16(c[2 * p + 1], a, bq + 2);
            }
        }

        {
            const int r0 = t * 64 + arow0 + (lane >> 2);
            #pragma unroll
            for (int j = 0; j < 8; j++) {
                int col = wc * 64 + j * 8 + 2 * (lane & 3);
                if (r0 < n_nodes) {
                    __half2 v = __floats2half2_rn(c[j][0] + bias[j][0],
                                                  c[j][1] + bias[j][1]);
                    *reinterpret_cast<uint32_t*>(&g_P16[(size_t)r0 * 256 + col]) =
                        *reinterpret_cast<uint32_t*>(&v);
                }
                if (r0 + 8 < n_nodes) {
                    __half2 v = __floats2half2_rn(c[j][2] + bias[j][0],
                                                  c[j][3] + bias[j][1]);
                    *reinterpret_cast<uint32_t*>(&g_P16[(size_t)(r0 + 8) * 256 + col]) =
                        *reinterpret_cast<uint32_t*>(&v);
                }
            }
        }
        __syncthreads();
        stage ^= 1;
    }
    cp_wait0();
}

// ---------------------------------------------------------------------------
// Kernel B: persistent fp16 edge MLP — ETILE=32, 256 threads, 2 CTAs/SM.
// 8 warps: wr=wid&1 (16 rows), wc=wid>>1 (24 cols = 3 n8-tiles).
// Depth-3 cp16 pipeline; register-resident W2; fused relu.
// ---------------------------------------------------------------------------
__global__ void __launch_bounds__(ETHREADS) edge_mma_kernel(
    const float* __restrict__ b2, float* __restrict__ out,
    int n_edges, int n_tiles)
{
    extern __shared__ char smem[];
    const uint32_t sbase = smem_u32(smem);
    float* OUTS = reinterpret_cast<float*>(smem + OFF_EOUTS);

    const int tid  = threadIdx.x;
    const int wid  = tid >> 5;
    const int lane = tid & 31;
    const int G    = gridDim.x;

    const int e_loc = tid >> 3;     // 0..31
    const int q     = tid & 7;      // 16-fp16 slice of 128-fp16 row

    const int wr = wid & 1;
    const int wc = wid >> 1;        // 0..3, 24 cols each
    const int arow0 = wr * 16;

    uint32_t bf[3][8][2];
    {
        const int n = wc * 24 + (lane >> 2);
        const int k2 = 2 * (lane & 3);
        #pragma unroll
        for (int j = 0; j < 3; j++) {
            const __half* rowp = &g_W2H[(n + j * 8) * DN];
            #pragma unroll
            for (int kk = 0; kk < 8; kk++) {
                bf[j][kk][0] = *reinterpret_cast<const uint32_t*>(rowp + kk * 16 + k2);
                bf[j][kk][1] = *reinterpret_cast<const uint32_t*>(rowp + kk * 16 + k2 + 8);
            }
        }
    }
    float bias[3][2];
    #pragma unroll
    for (int j = 0; j < 3; j++) {
        int col = wc * 24 + j * 8 + 2 * (lane & 3);
        bias[j][0] = (col     < CN) ? b2[col]     : 0.f;
        bias[j][1] = (col + 1 < CN) ? b2[col + 1] : 0.f;
    }

    auto prefetch = [&](int t, int s) {
        if (t < n_tiles) {
            int eg = t * ETILE + e_loc;
            int si = 0, di = 0;
            if (eg < n_edges) { si = __ldg(&g_src32[eg]); di = __ldg(&g_dst32[eg]); }
            const __half* us = &g_P16[(size_t)si * 256 + q * 16];
            const __half* vs = &g_P16[(size_t)di * 256 + 128 + q * 16];
            uint32_t ud = sbase + s * ESTAGE_B + e_loc * U_PITCH_B + q * 32;
            uint32_t vd = ud + 8704;   // 32 rows * 272
            cp16(ud,      us);
            cp16(ud + 16, us + 8);
            cp16(vd,      vs);
            cp16(vd + 16, vs + 8);
        }
        cp_commit();
    };

    const uint32_t a_off = (uint32_t)(arow0 + (lane & 15)) * U_PITCH_B + (lane >> 4) * 16;

    int stage = 0;
    prefetch(blockIdx.x, 0);
    prefetch(blockIdx.x + G, 1);

    for (int t = blockIdx.x; t < n_tiles; t += G) {
        prefetch(t + 2 * G, (stage + 2) % 3);
        cp_wait2();
        __syncthreads();

        const uint32_t ub = sbase + stage * ESTAGE_B + a_off;
        const uint32_t vb = ub + 8704;

        float c[3][4];
        #pragma unroll
        for (int j = 0; j < 3; j++)
            #pragma unroll
            for (int r = 0; r < 4; r++) c[j][r] = 0.f;

        #pragma unroll
        for (int kk = 0; kk < 8; kk++) {
            uint32_t au[4], av[4], a[4];
            ldmx4(au, ub + kk * 32);
            ldmx4(av, vb + kk * 32);
            #pragma unroll
            for (int r = 0; r < 4; r++)
                a[r] = hrelu2_(hadd2_(au[r], av[r]));
            #pragma unroll
            for (int j = 0; j < 3; j++)
                mma_f16(c[j], a, bf[j][kk]);
        }
        __syncthreads();   // U/V[stage] reads done before its refill next iter

        {
            const int row = arow0 + (lane >> 2);
            #pragma unroll
            for (int j = 0; j < 3; j++) {
                int col = wc * 24 + j * 8 + 2 * (lane & 3);
                if (col < CN) {
                    OUTS[row * CN + col]       = c[j][0] + bias[j][0];
                    OUTS[(row + 8) * CN + col] = c[j][2] + bias[j][0];
                }
                if (col + 1 < CN) {
                    OUTS[row * CN + col + 1]       = c[j][1] + bias[j][1];
                    OUTS[(row + 8) * CN + col + 1] = c[j][3] + bias[j][1];
                }
            }
        }
        __syncthreads();

        int e0 = t * ETILE;
        int valid = n_edges - e0;
        if (valid > ETILE) valid = ETILE;
        float* dstp = out + (size_t)e0 * CN;
        if (valid == ETILE) {
            const float4* s4 = reinterpret_cast<const float4*>(OUTS);
            float4* d4 = reinterpret_cast<float4*>(dstp);
            #pragma unroll
            for (int i = tid; i < ETILE * CN / 4; i += ETHREADS) d4[i] = s4[i];
        } else {
            for (int i = tid; i < valid * CN; i += ETHREADS) dstp[i] = OUTS[i];
        }
        __syncthreads();
        stage = (stage + 1) % 3;
    }
    cp_wait0();
}

// ---------------------------------------------------------------------------
extern "C" void kernel_launch(void* const* d_in, const int* in_sizes, int n_in,
                              void* d_out, int out_size)
{
    const float* h   = (const float*)d_in[0];
    const float* W1  = (const float*)d_in[1];
    const float* b1  = (const float*)d_in[2];
    const float* W2  = (const float*)d_in[3];
    const float* b2  = (const float*)d_in[4];
    const void*  src = d_in[5];
    const void*  dst = d_in[6];
    float* out = (float*)d_out;

    const int n_nodes = in_sizes[0] / DN;
    const int n_edges = in_sizes[5];

    static int n_sm = 0;
    if (n_sm == 0) {
        cudaDeviceGetAttribute(&n_sm, cudaDevAttrMultiProcessorCount, 0);
        if (n_sm <= 0) n_sm = 148;
    }

    sniff_kernel<<<1, 256>>>(src, n_edges, n_nodes);
    convert_kernel<<<(n_edges + 255) / 256, 256>>>(src, dst, n_edges);
    w2h_kernel<<<(NP * DN + 255) / 256, 256>>>(W2);

    cudaFuncSetAttribute(node_mma_kernel, cudaFuncAttributeMaxDynamicSharedMemorySize, SMEM_NODE_BYTES);
    cudaFuncSetAttribute(edge_mma_kernel, cudaFuncAttributeMaxDynamicSharedMemorySize, SMEM_EDGE_BYTES);

    int n_tiles_node = (n_nodes + 63) / 64;
    node_mma_kernel<<<n_sm, 512, SMEM_NODE_BYTES>>>(h, W1, b1, n_nodes, n_tiles_node);

    int n_tiles = (n_edges + ETILE - 1) / ETILE;
    edge_mma_kernel<<<2 * n_sm, ETHREADS, SMEM_EDGE_BYTES>>>(b2, out, n_edges, n_tiles);
}